// round 4
// baseline (speedup 1.0000x reference)
#include <cuda_runtime.h>
#include <cstdint>

// ---------------------------------------------------------------------------
// AdjGenerator: adj = (mean_h sigmoid(log(relu(Wg·PE)+1e-6) + (q·kT)/32) > 0.5)
// N = M = 2048, D = 1024, EMB = 64, HEADS = 16
// ---------------------------------------------------------------------------

#define NDIM 2048
#define MDIM 2048
#define DDIM 1024
#define EMB  64
#define HEADS 16

__device__ float g_q[NDIM * DDIM];
__device__ float g_k[MDIM * DDIM];
__device__ float g_aff[NDIM * MDIM];

typedef unsigned long long ull;

// packed pos-gate weights: c_wg2[e*HEADS+h] = dup2(Wg_w[h,e])
__constant__ ull   c_wg2[EMB * HEADS];
__constant__ float c_wgb[HEADS];
__device__   ull   g_wgpack[EMB * HEADS];
__device__   float g_bpack[HEADS];

// ---- packed f32x2 helpers (Blackwell FFMA2, PTX-only) ---------------------
__device__ __forceinline__ ull dup2(float v) {
    ull r;
    asm("mov.b64 %0, {%1, %1};" : "=l"(r) : "f"(v));
    return r;
}
__device__ __forceinline__ void fma2(ull& d, ull a, ull b) {
    asm("fma.rn.f32x2 %0, %1, %2, %0;" : "+l"(d) : "l"(a), "l"(b));
}
__device__ __forceinline__ float2 unpack2(ull v) {
    float2 f;
    asm("mov.b64 {%0, %1}, %2;" : "=f"(f.x), "=f"(f.y) : "l"(v));
    return f;
}

// ---------------------------------------------------------------------------
// prep: transpose + duplicate Wg into scratch (then memcpy'd to constant)
// ---------------------------------------------------------------------------
__global__ void prep_kernel(const float* __restrict__ Wg_w,
                            const float* __restrict__ Wg_b)
{
    int idx = blockIdx.x * 256 + threadIdx.x;
    if (idx < EMB * HEADS) {
        int e = idx / HEADS, h = idx % HEADS;
        g_wgpack[idx] = dup2(Wg_w[h * EMB + e]);
    }
    if (idx < HEADS) g_bpack[idx] = Wg_b[idx];
}

// ---------------------------------------------------------------------------
// SGEMM NT: C[r,c] = scale * sum_d A[r,d]*B[c,d] + bias[c]
// BM=BN=128, BK=16, 256 threads, 8x8 per thread, f32x2 accumulators.
// outsel 0: fused q/k (gridDim.z=2 picks operand set); outsel 2: aff.
// ---------------------------------------------------------------------------
#define BM 128
#define BN 128
#define BK 16

__global__ void __launch_bounds__(256)
gemm_nt_kernel(const float* __restrict__ A0, const float* __restrict__ B0,
               const float* __restrict__ bias0,
               const float* __restrict__ A1, const float* __restrict__ B1,
               const float* __restrict__ bias1,
               int Ncols, float scale, int outsel)
{
    const float* A;
    const float* B;
    const float* bias;
    float* C;
    if (outsel == 0) {
        if (blockIdx.z == 0) { A = A0; B = B0; bias = bias0; C = g_q; }
        else                 { A = A1; B = B1; bias = bias1; C = g_k; }
    } else {
        A = g_q; B = g_k; bias = nullptr; C = g_aff;
    }

    const int K = DDIM;

    __shared__ float As[BK][BM + 4];
    __shared__ float Bs[BK][BN + 4];

    const int tid = threadIdx.x;
    const int tx = tid & 15;
    const int ty = tid >> 4;
    const int row0 = blockIdx.y * BM;
    const int col0 = blockIdx.x * BN;

    const float* Abase = A + (size_t)row0 * K;
    const float* Bbase = B + (size_t)col0 * K;

    const int ar0 = tid >> 2,          ac0 = (tid & 3) * 4;
    const int ar1 = (tid + 256) >> 2,  ac1 = ((tid + 256) & 3) * 4;

    float4 av0 = *(const float4*)&Abase[(size_t)ar0 * K + ac0];
    float4 av1 = *(const float4*)&Abase[(size_t)ar1 * K + ac1];
    float4 bv0 = *(const float4*)&Bbase[(size_t)ar0 * K + ac0];
    float4 bv1 = *(const float4*)&Bbase[(size_t)ar1 * K + ac1];

    As[ac0 + 0][ar0] = av0.x; As[ac0 + 1][ar0] = av0.y;
    As[ac0 + 2][ar0] = av0.z; As[ac0 + 3][ar0] = av0.w;
    As[ac1 + 0][ar1] = av1.x; As[ac1 + 1][ar1] = av1.y;
    As[ac1 + 2][ar1] = av1.z; As[ac1 + 3][ar1] = av1.w;
    Bs[ac0 + 0][ar0] = bv0.x; Bs[ac0 + 1][ar0] = bv0.y;
    Bs[ac0 + 2][ar0] = bv0.z; Bs[ac0 + 3][ar0] = bv0.w;
    Bs[ac1 + 0][ar1] = bv1.x; Bs[ac1 + 1][ar1] = bv1.y;
    Bs[ac1 + 2][ar1] = bv1.z; Bs[ac1 + 3][ar1] = bv1.w;
    __syncthreads();

    ull c2[8][4];
#pragma unroll
    for (int i = 0; i < 8; i++)
#pragma unroll
        for (int j = 0; j < 4; j++) c2[i][j] = 0ull;

    for (int kc = BK; kc <= K; kc += BK) {
        if (kc < K) {
            av0 = *(const float4*)&Abase[(size_t)ar0 * K + kc + ac0];
            av1 = *(const float4*)&Abase[(size_t)ar1 * K + kc + ac1];
            bv0 = *(const float4*)&Bbase[(size_t)ar0 * K + kc + ac0];
            bv1 = *(const float4*)&Bbase[(size_t)ar1 * K + kc + ac1];
        }
#pragma unroll
        for (int k = 0; k < BK; k++) {
            float4 aA = *(const float4*)&As[k][ty * 8];
            float4 aB = *(const float4*)&As[k][ty * 8 + 4];
            ull a2[8];
            a2[0] = dup2(aA.x); a2[1] = dup2(aA.y); a2[2] = dup2(aA.z); a2[3] = dup2(aA.w);
            a2[4] = dup2(aB.x); a2[5] = dup2(aB.y); a2[6] = dup2(aB.z); a2[7] = dup2(aB.w);
            ulonglong2 b01 = *(const ulonglong2*)&Bs[k][tx * 8];
            ulonglong2 b23 = *(const ulonglong2*)&Bs[k][tx * 8 + 4];
            ull b2[4] = { b01.x, b01.y, b23.x, b23.y };
#pragma unroll
            for (int i = 0; i < 8; i++) {
#pragma unroll
                for (int j = 0; j < 4; j++) fma2(c2[i][j], a2[i], b2[j]);
            }
        }
        if (kc < K) {
            __syncthreads();
            As[ac0 + 0][ar0] = av0.x; As[ac0 + 1][ar0] = av0.y;
            As[ac0 + 2][ar0] = av0.z; As[ac0 + 3][ar0] = av0.w;
            As[ac1 + 0][ar1] = av1.x; As[ac1 + 1][ar1] = av1.y;
            As[ac1 + 2][ar1] = av1.z; As[ac1 + 3][ar1] = av1.w;
            Bs[ac0 + 0][ar0] = bv0.x; Bs[ac0 + 1][ar0] = bv0.y;
            Bs[ac0 + 2][ar0] = bv0.z; Bs[ac0 + 3][ar0] = bv0.w;
            Bs[ac1 + 0][ar1] = bv1.x; Bs[ac1 + 1][ar1] = bv1.y;
            Bs[ac1 + 2][ar1] = bv1.z; Bs[ac1 + 3][ar1] = bv1.w;
            __syncthreads();
        }
    }

#pragma unroll
    for (int i = 0; i < 8; i++) {
        size_t r = (size_t)(row0 + ty * 8 + i);
        float* crow = C + r * (size_t)Ncols + col0 + tx * 8;
        float2 f0 = unpack2(c2[i][0]);
        float2 f1 = unpack2(c2[i][1]);
        float2 f2v = unpack2(c2[i][2]);
        float2 f3 = unpack2(c2[i][3]);
        float4 o0, o1;
        if (bias) {
            const float* bp = bias + col0 + tx * 8;
            o0 = make_float4(f0.x * scale + bp[0], f0.y * scale + bp[1],
                             f1.x * scale + bp[2], f1.y * scale + bp[3]);
            o1 = make_float4(f2v.x * scale + bp[4], f2v.y * scale + bp[5],
                             f3.x * scale + bp[6], f3.y * scale + bp[7]);
        } else {
            o0 = make_float4(f0.x * scale, f0.y * scale, f1.x * scale, f1.y * scale);
            o1 = make_float4(f2v.x * scale, f2v.y * scale, f3.x * scale, f3.y * scale);
        }
        *(float4*)&crow[0] = o0;
        *(float4*)&crow[4] = o1;
    }
}

// ---------------------------------------------------------------------------
// Pos-gate stream + fused epilogue.
// Weights in __constant__ (uniform LDCU path -> zero L1 wavefronts).
// Each thread: 2 m-elements, 16 packed f32x2 accs, prefetch depth 8, __ldcs.
// sigmoid(log(w)+aff) == w / (w + exp(-aff));  sum_h > 8 -> 1.
// ---------------------------------------------------------------------------
__global__ void __launch_bounds__(256, 3)
pos_epilogue_kernel(const float* __restrict__ PE, float* __restrict__ out)
{
    const int n = blockIdx.y;
    const int m = blockIdx.x * 512 + threadIdx.x * 2;

    // plane stride: NDIM*MDIM floats = 2^22 floats = 2^21 ull
    const ull* pe = (const ull*)PE + (((size_t)n * MDIM + m) >> 1);

    ull acc[HEADS];
#pragma unroll
    for (int h = 0; h < HEADS; h++) acc[h] = 0ull;

    ull buf[8];
#pragma unroll
    for (int i = 0; i < 8; i++) buf[i] = __ldcs(pe + ((size_t)i << 21));

    for (int eo = 0; eo < EMB; eo += 8) {
#pragma unroll
        for (int i = 0; i < 8; i++) {
            ull pv = buf[i];
            int en_ = eo + 8 + i;
            if (en_ < EMB) buf[i] = __ldcs(pe + ((size_t)en_ << 21));
            const ull* w = &c_wg2[(eo + i) * HEADS];
#pragma unroll
            for (int h = 0; h < HEADS; h++) fma2(acc[h], w[h], pv);
        }
    }

    // fused sigmoid-mean-threshold
    const float2 av = *(const float2*)&g_aff[(size_t)n * MDIM + m];
    const float L2E = 1.4426950408889634f;
    float en0 = exp2f(-av.x * L2E);
    float en1 = exp2f(-av.y * L2E);

    float s0 = 0.f, s1 = 0.f;
#pragma unroll
    for (int h = 0; h < HEADS; h++) {
        float bh = c_wgb[h];
        float2 p = unpack2(acc[h]);
        float w0 = fmaxf(p.x + bh, 0.f) + 1e-6f; s0 += __fdividef(w0, w0 + en0);
        float w1 = fmaxf(p.y + bh, 0.f) + 1e-6f; s1 += __fdividef(w1, w1 + en1);
    }

    float2 o;
    o.x = (s0 > 8.0f) ? 1.0f : 0.0f;
    o.y = (s1 > 8.0f) ? 1.0f : 0.0f;
    *(float2*)&out[(size_t)n * MDIM + m] = o;
}

// ---------------------------------------------------------------------------
extern "C" void kernel_launch(void* const* d_in, const int* in_sizes, int n_in,
                              void* d_out, int out_size)
{
    (void)in_sizes; (void)n_in; (void)out_size;
    const float* ref_feat = (const float*)d_in[0];
    const float* sup_feat = (const float*)d_in[1];
    const float* PE       = (const float*)d_in[2];
    const float* Wg_w     = (const float*)d_in[3];
    const float* Wg_b     = (const float*)d_in[4];
    const float* Wq_w     = (const float*)d_in[5];
    const float* Wq_b     = (const float*)d_in[6];
    const float* Wk_w     = (const float*)d_in[7];
    const float* Wk_b     = (const float*)d_in[8];
    float* out = (float*)d_out;

    // pack pos-gate weights, then stage into constant memory (D2D memcpy node)
    prep_kernel<<<4, 256>>>(Wg_w, Wg_b);
    void* src_w = nullptr;
    void* src_b = nullptr;
    cudaGetSymbolAddress(&src_w, g_wgpack);
    cudaGetSymbolAddress(&src_b, g_bpack);
    cudaMemcpyToSymbolAsync(c_wg2, src_w, sizeof(ull) * EMB * HEADS, 0,
                            cudaMemcpyDeviceToDevice, 0);
    cudaMemcpyToSymbolAsync(c_wgb, src_b, sizeof(float) * HEADS, 0,
                            cudaMemcpyDeviceToDevice, 0);

    // fused q/k GEMM: z=0 -> q = ref@WqT+bq, z=1 -> k = sup@WkT+bk
    gemm_nt_kernel<<<dim3(DDIM / BN, NDIM / BM, 2), 256>>>(
        ref_feat, Wq_w, Wq_b, sup_feat, Wk_w, Wk_b, DDIM, 1.0f, 0);
    // aff = (q @ kT) / 32
    gemm_nt_kernel<<<dim3(MDIM / BN, NDIM / BM, 1), 256>>>(
        nullptr, nullptr, nullptr, nullptr, nullptr, nullptr, MDIM, 0.03125f, 2);
    // pos stream + fused epilogue
    pos_epilogue_kernel<<<dim3(MDIM / 512, NDIM), 256>>>(PE, out);
}

// round 5
// speedup vs baseline: 1.2877x; 1.2877x over previous
#include <cuda_runtime.h>
#include <cstdint>

// ---------------------------------------------------------------------------
// AdjGenerator: adj = (mean_h sigmoid(log(relu(Wg·PE)+1e-6) + (q·kT)/32) > 0.5)
// N = M = 2048, D = 1024, EMB = 64, HEADS = 16
// ---------------------------------------------------------------------------

#define NDIM 2048
#define MDIM 2048
#define DDIM 1024
#define EMB  64
#define HEADS 16

__device__ float g_q[NDIM * DDIM];
__device__ float g_k[MDIM * DDIM];
__device__ float g_aff[NDIM * MDIM];

typedef unsigned long long ull;

// ---- packed f32x2 helpers (Blackwell FFMA2, PTX-only) ---------------------
__device__ __forceinline__ ull dup2(float v) {
    ull r;
    asm("mov.b64 %0, {%1, %1};" : "=l"(r) : "f"(v));
    return r;
}
__device__ __forceinline__ void fma2(ull& d, ull a, ull b) {
    asm("fma.rn.f32x2 %0, %1, %2, %0;" : "+l"(d) : "l"(a), "l"(b));
}
__device__ __forceinline__ float2 unpack2(ull v) {
    float2 f;
    asm("mov.b64 {%0, %1}, %2;" : "=f"(f.x), "=f"(f.y) : "l"(v));
    return f;
}
// streaming (evict-first) 16B global load
__device__ __forceinline__ void ldcs_v2u64(const void* p, ull& a, ull& b) {
    asm("ld.global.cs.v2.u64 {%0, %1}, [%2];" : "=l"(a), "=l"(b) : "l"(p));
}

// ---------------------------------------------------------------------------
// SGEMM NT: C[r,c] = scale * sum_d A[r,d]*B[c,d] + bias[c]
// BM=BN=128, BK=16, 256 threads, 8x8 per thread, f32x2 accumulators.
// outsel 0: fused q/k (gridDim.z=2 picks operand set); outsel 2: aff.
// ---------------------------------------------------------------------------
#define BM 128
#define BN 128
#define BK 16

__global__ void __launch_bounds__(256)
gemm_nt_kernel(const float* __restrict__ A0, const float* __restrict__ B0,
               const float* __restrict__ bias0,
               const float* __restrict__ A1, const float* __restrict__ B1,
               const float* __restrict__ bias1,
               int Ncols, float scale, int outsel)
{
    const float* A;
    const float* B;
    const float* bias;
    float* C;
    if (outsel == 0) {
        if (blockIdx.z == 0) { A = A0; B = B0; bias = bias0; C = g_q; }
        else                 { A = A1; B = B1; bias = bias1; C = g_k; }
    } else {
        A = g_q; B = g_k; bias = nullptr; C = g_aff;
    }

    const int K = DDIM;

    __shared__ float As[BK][BM + 4];
    __shared__ float Bs[BK][BN + 4];

    const int tid = threadIdx.x;
    const int tx = tid & 15;
    const int ty = tid >> 4;
    const int row0 = blockIdx.y * BM;
    const int col0 = blockIdx.x * BN;

    const float* Abase = A + (size_t)row0 * K;
    const float* Bbase = B + (size_t)col0 * K;

    const int ar0 = tid >> 2,          ac0 = (tid & 3) * 4;
    const int ar1 = (tid + 256) >> 2,  ac1 = ((tid + 256) & 3) * 4;

    float4 av0 = *(const float4*)&Abase[(size_t)ar0 * K + ac0];
    float4 av1 = *(const float4*)&Abase[(size_t)ar1 * K + ac1];
    float4 bv0 = *(const float4*)&Bbase[(size_t)ar0 * K + ac0];
    float4 bv1 = *(const float4*)&Bbase[(size_t)ar1 * K + ac1];

    As[ac0 + 0][ar0] = av0.x; As[ac0 + 1][ar0] = av0.y;
    As[ac0 + 2][ar0] = av0.z; As[ac0 + 3][ar0] = av0.w;
    As[ac1 + 0][ar1] = av1.x; As[ac1 + 1][ar1] = av1.y;
    As[ac1 + 2][ar1] = av1.z; As[ac1 + 3][ar1] = av1.w;
    Bs[ac0 + 0][ar0] = bv0.x; Bs[ac0 + 1][ar0] = bv0.y;
    Bs[ac0 + 2][ar0] = bv0.z; Bs[ac0 + 3][ar0] = bv0.w;
    Bs[ac1 + 0][ar1] = bv1.x; Bs[ac1 + 1][ar1] = bv1.y;
    Bs[ac1 + 2][ar1] = bv1.z; Bs[ac1 + 3][ar1] = bv1.w;
    __syncthreads();

    ull c2[8][4];
#pragma unroll
    for (int i = 0; i < 8; i++)
#pragma unroll
        for (int j = 0; j < 4; j++) c2[i][j] = 0ull;

    for (int kc = BK; kc <= K; kc += BK) {
        if (kc < K) {
            av0 = *(const float4*)&Abase[(size_t)ar0 * K + kc + ac0];
            av1 = *(const float4*)&Abase[(size_t)ar1 * K + kc + ac1];
            bv0 = *(const float4*)&Bbase[(size_t)ar0 * K + kc + ac0];
            bv1 = *(const float4*)&Bbase[(size_t)ar1 * K + kc + ac1];
        }
#pragma unroll
        for (int k = 0; k < BK; k++) {
            float4 aA = *(const float4*)&As[k][ty * 8];
            float4 aB = *(const float4*)&As[k][ty * 8 + 4];
            ull a2[8];
            a2[0] = dup2(aA.x); a2[1] = dup2(aA.y); a2[2] = dup2(aA.z); a2[3] = dup2(aA.w);
            a2[4] = dup2(aB.x); a2[5] = dup2(aB.y); a2[6] = dup2(aB.z); a2[7] = dup2(aB.w);
            ulonglong2 b01 = *(const ulonglong2*)&Bs[k][tx * 8];
            ulonglong2 b23 = *(const ulonglong2*)&Bs[k][tx * 8 + 4];
            ull b2[4] = { b01.x, b01.y, b23.x, b23.y };
#pragma unroll
            for (int i = 0; i < 8; i++) {
#pragma unroll
                for (int j = 0; j < 4; j++) fma2(c2[i][j], a2[i], b2[j]);
            }
        }
        if (kc < K) {
            __syncthreads();
            As[ac0 + 0][ar0] = av0.x; As[ac0 + 1][ar0] = av0.y;
            As[ac0 + 2][ar0] = av0.z; As[ac0 + 3][ar0] = av0.w;
            As[ac1 + 0][ar1] = av1.x; As[ac1 + 1][ar1] = av1.y;
            As[ac1 + 2][ar1] = av1.z; As[ac1 + 3][ar1] = av1.w;
            Bs[ac0 + 0][ar0] = bv0.x; Bs[ac0 + 1][ar0] = bv0.y;
            Bs[ac0 + 2][ar0] = bv0.z; Bs[ac0 + 3][ar0] = bv0.w;
            Bs[ac1 + 0][ar1] = bv1.x; Bs[ac1 + 1][ar1] = bv1.y;
            Bs[ac1 + 2][ar1] = bv1.z; Bs[ac1 + 3][ar1] = bv1.w;
            __syncthreads();
        }
    }

#pragma unroll
    for (int i = 0; i < 8; i++) {
        size_t r = (size_t)(row0 + ty * 8 + i);
        float* crow = C + r * (size_t)Ncols + col0 + tx * 8;
        float2 f0 = unpack2(c2[i][0]);
        float2 f1 = unpack2(c2[i][1]);
        float2 f2v = unpack2(c2[i][2]);
        float2 f3 = unpack2(c2[i][3]);
        float4 o0, o1;
        if (bias) {
            const float* bp = bias + col0 + tx * 8;
            o0 = make_float4(f0.x * scale + bp[0], f0.y * scale + bp[1],
                             f1.x * scale + bp[2], f1.y * scale + bp[3]);
            o1 = make_float4(f2v.x * scale + bp[4], f2v.y * scale + bp[5],
                             f3.x * scale + bp[6], f3.y * scale + bp[7]);
        } else {
            o0 = make_float4(f0.x * scale, f0.y * scale, f1.x * scale, f1.y * scale);
            o1 = make_float4(f2v.x * scale, f2v.y * scale, f3.x * scale, f3.y * scale);
        }
        *(float4*)&crow[0] = o0;
        *(float4*)&crow[4] = o1;
    }
}

// ---------------------------------------------------------------------------
// Pos-gate stream + fused epilogue.
// T=4 m-elements per thread: each LDS.128 weight load (2 heads) feeds 4 fma2
// (half the weight traffic per FMA vs T=2). __launch_bounds__(256,2) caps
// regs at 128 -> 16 warps/SM (R2's layout died at 134 regs / 8 warps).
// Prefetch depth 4 of 16B streaming loads (32KB/SM outstanding > 18KB needed).
// sigmoid(log(w)+aff) == w / (w + exp(-aff));  sum_h > 8 -> 1.
// ---------------------------------------------------------------------------
__global__ void __launch_bounds__(256, 2)
pos_epilogue_kernel(const float* __restrict__ PE, const float* __restrict__ Wg_w,
                    const float* __restrict__ Wg_b, float* __restrict__ out)
{
    __shared__ ull sh_wg2[EMB][HEADS];   // dup'd f32x2 per (e, h), 8 KB
    __shared__ float sh_b[HEADS];

    const int tid = threadIdx.x;
    for (int idx = tid; idx < EMB * HEADS; idx += 256) {
        int e = idx >> 4, h = idx & 15;
        sh_wg2[e][h] = dup2(Wg_w[h * EMB + e]);
    }
    if (tid < HEADS) sh_b[tid] = Wg_b[tid];
    __syncthreads();

    const int n = blockIdx.y;
    const int m = blockIdx.x * 1024 + tid * 4;

    // plane stride: NDIM*MDIM floats = 2^22 floats = 2^20 * 16B
    const char* pe = (const char*)(PE + (size_t)n * MDIM + m);
    const size_t PLANE = (size_t)NDIM * MDIM * 4;   // bytes

    ull acc[HEADS][2];
#pragma unroll
    for (int h = 0; h < HEADS; h++) { acc[h][0] = 0ull; acc[h][1] = 0ull; }

    // depth-4 software pipeline of 16B streaming loads
    ull bx[4], by[4];
#pragma unroll
    for (int i = 0; i < 4; i++) ldcs_v2u64(pe + (size_t)i * PLANE, bx[i], by[i]);

    for (int eo = 0; eo < EMB; eo += 4) {
#pragma unroll
        for (int i = 0; i < 4; i++) {
            ull pvx = bx[i], pvy = by[i];
            int en_ = eo + 4 + i;
            if (en_ < EMB) ldcs_v2u64(pe + (size_t)en_ * PLANE, bx[i], by[i]);
            const ulonglong2* wrow = (const ulonglong2*)sh_wg2[eo + i];
#pragma unroll
            for (int h2 = 0; h2 < 8; h2++) {
                ulonglong2 w = wrow[h2];          // LDS.128: 2 heads
                fma2(acc[2 * h2][0],     w.x, pvx);
                fma2(acc[2 * h2][1],     w.x, pvy);
                fma2(acc[2 * h2 + 1][0], w.y, pvx);
                fma2(acc[2 * h2 + 1][1], w.y, pvy);
            }
        }
    }

    // fused sigmoid-mean-threshold over 4 m-elements
    const float4 av = *(const float4*)&g_aff[(size_t)n * MDIM + m];
    const float L2E = 1.4426950408889634f;
    float en0 = exp2f(-av.x * L2E);
    float en1 = exp2f(-av.y * L2E);
    float en2 = exp2f(-av.z * L2E);
    float en3 = exp2f(-av.w * L2E);

    float s0 = 0.f, s1 = 0.f, s2 = 0.f, s3 = 0.f;
#pragma unroll
    for (int h = 0; h < HEADS; h++) {
        float bh = sh_b[h];
        float2 p0 = unpack2(acc[h][0]);
        float2 p1 = unpack2(acc[h][1]);
        float w;
        w = fmaxf(p0.x + bh, 0.f) + 1e-6f; s0 += __fdividef(w, w + en0);
        w = fmaxf(p0.y + bh, 0.f) + 1e-6f; s1 += __fdividef(w, w + en1);
        w = fmaxf(p1.x + bh, 0.f) + 1e-6f; s2 += __fdividef(w, w + en2);
        w = fmaxf(p1.y + bh, 0.f) + 1e-6f; s3 += __fdividef(w, w + en3);
    }

    float4 o;
    o.x = (s0 > 8.0f) ? 1.0f : 0.0f;
    o.y = (s1 > 8.0f) ? 1.0f : 0.0f;
    o.z = (s2 > 8.0f) ? 1.0f : 0.0f;
    o.w = (s3 > 8.0f) ? 1.0f : 0.0f;
    *(float4*)&out[(size_t)n * MDIM + m] = o;
}

// ---------------------------------------------------------------------------
extern "C" void kernel_launch(void* const* d_in, const int* in_sizes, int n_in,
                              void* d_out, int out_size)
{
    (void)in_sizes; (void)n_in; (void)out_size;
    const float* ref_feat = (const float*)d_in[0];
    const float* sup_feat = (const float*)d_in[1];
    const float* PE       = (const float*)d_in[2];
    const float* Wg_w     = (const float*)d_in[3];
    const float* Wg_b     = (const float*)d_in[4];
    const float* Wq_w     = (const float*)d_in[5];
    const float* Wq_b     = (const float*)d_in[6];
    const float* Wk_w     = (const float*)d_in[7];
    const float* Wk_b     = (const float*)d_in[8];
    float* out = (float*)d_out;

    // fused q/k GEMM: z=0 -> q = ref@WqT+bq, z=1 -> k = sup@WkT+bk
    gemm_nt_kernel<<<dim3(DDIM / BN, NDIM / BM, 2), 256>>>(
        ref_feat, Wq_w, Wq_b, sup_feat, Wk_w, Wk_b, DDIM, 1.0f, 0);
    // aff = (q @ kT) / 32
    gemm_nt_kernel<<<dim3(MDIM / BN, NDIM / BM, 1), 256>>>(
        nullptr, nullptr, nullptr, nullptr, nullptr, nullptr, MDIM, 0.03125f, 2);
    // pos stream + fused epilogue
    pos_epilogue_kernel<<<dim3(MDIM / 1024, NDIM), 256>>>(PE, Wg_w, Wg_b, out);
}

// round 6
// speedup vs baseline: 1.3716x; 1.0652x over previous
#include <cuda_runtime.h>
#include <cstdint>

// ---------------------------------------------------------------------------
// AdjGenerator: adj = (mean_h sigmoid(log(relu(Wg·PE)+1e-6) + (q·kT)/32) > 0.5)
// N = M = 2048, D = 1024, EMB = 64, HEADS = 16
// ---------------------------------------------------------------------------

#define NDIM 2048
#define MDIM 2048
#define DDIM 1024
#define EMB  64
#define HEADS 16

__device__ float g_q[NDIM * DDIM];
__device__ float g_k[MDIM * DDIM];
__device__ float g_aff[NDIM * MDIM];

typedef unsigned long long ull;

// ---- packed f32x2 helpers (Blackwell FFMA2, PTX-only) ---------------------
__device__ __forceinline__ ull dup2(float v) {
    ull r;
    asm("mov.b64 %0, {%1, %1};" : "=l"(r) : "f"(v));
    return r;
}
__device__ __forceinline__ void fma2(ull& d, ull a, ull b) {
    asm("fma.rn.f32x2 %0, %1, %2, %0;" : "+l"(d) : "l"(a), "l"(b));
}
__device__ __forceinline__ float2 unpack2(ull v) {
    float2 f;
    asm("mov.b64 {%0, %1}, %2;" : "=f"(f.x), "=f"(f.y) : "l"(v));
    return f;
}
// streaming (evict-first) 16B global load
__device__ __forceinline__ void ldcs_v2u64(const void* p, ull& a, ull& b) {
    asm("ld.global.cs.v2.u64 {%0, %1}, [%2];" : "=l"(a), "=l"(b) : "l"(p));
}

// ---------------------------------------------------------------------------
// SGEMM NT: C[r,c] = scale * sum_d A[r,d]*B[c,d] + bias[c]
// 512 threads, BM=128, BN=256, BK=16, 8x8 per thread (16x32 thread grid).
// One CTA/SM with 16 warps -> 4 warps/SMSP of latency hiding at the same
// LDS:FMA parity as the 256-thread version. Regs must stay <=128 (RF-exact).
// outsel 0: fused q/k (gridDim.z picks operand set); outsel 2: aff.
// ---------------------------------------------------------------------------
#define BM 128
#define BN 256
#define BK 16

__global__ void __launch_bounds__(512, 1)
gemm_nt_kernel(const float* __restrict__ A0, const float* __restrict__ B0,
               const float* __restrict__ bias0,
               const float* __restrict__ A1, const float* __restrict__ B1,
               const float* __restrict__ bias1,
               int Ncols, float scale, int outsel)
{
    const float* A;
    const float* B;
    const float* bias;
    float* C;
    if (outsel == 0) {
        if (blockIdx.z == 0) { A = A0; B = B0; bias = bias0; C = g_q; }
        else                 { A = A1; B = B1; bias = bias1; C = g_k; }
    } else {
        A = g_q; B = g_k; bias = nullptr; C = g_aff;
    }

    const int K = DDIM;

    __shared__ float As[BK][BM + 4];   //  8.4 KB
    __shared__ float Bs[BK][BN + 4];   // 16.6 KB

    const int tid = threadIdx.x;
    const int tx = tid & 31;        // 0..31 -> col block of 8 (256)
    const int ty = tid >> 5;        // 0..15 -> row block of 8 (128)
    const int row0 = blockIdx.y * BM;
    const int col0 = blockIdx.x * BN;

    const float* Abase = A + (size_t)row0 * K;
    const float* Bbase = B + (size_t)col0 * K;

    // A: 512 float4 slots, 1/thread. B: 1024 slots, 2/thread.
    const int ar0 = tid >> 2,          ac0 = (tid & 3) * 4;       // A row 0..127
    const int br1 = (tid + 512) >> 2,  bc1 = ((tid + 512) & 3) * 4; // B row 128..255

    float4 av0 = *(const float4*)&Abase[(size_t)ar0 * K + ac0];
    float4 bv0 = *(const float4*)&Bbase[(size_t)ar0 * K + ac0];
    float4 bv1 = *(const float4*)&Bbase[(size_t)br1 * K + bc1];

    As[ac0 + 0][ar0] = av0.x; As[ac0 + 1][ar0] = av0.y;
    As[ac0 + 2][ar0] = av0.z; As[ac0 + 3][ar0] = av0.w;
    Bs[ac0 + 0][ar0] = bv0.x; Bs[ac0 + 1][ar0] = bv0.y;
    Bs[ac0 + 2][ar0] = bv0.z; Bs[ac0 + 3][ar0] = bv0.w;
    Bs[bc1 + 0][br1] = bv1.x; Bs[bc1 + 1][br1] = bv1.y;
    Bs[bc1 + 2][br1] = bv1.z; Bs[bc1 + 3][br1] = bv1.w;
    __syncthreads();

    ull c2[8][4];
#pragma unroll
    for (int i = 0; i < 8; i++)
#pragma unroll
        for (int j = 0; j < 4; j++) c2[i][j] = 0ull;

    for (int kc = BK; kc <= K; kc += BK) {
        if (kc < K) {
            av0 = *(const float4*)&Abase[(size_t)ar0 * K + kc + ac0];
            bv0 = *(const float4*)&Bbase[(size_t)ar0 * K + kc + ac0];
            bv1 = *(const float4*)&Bbase[(size_t)br1 * K + kc + bc1];
        }
#pragma unroll
        for (int k = 0; k < BK; k++) {
            float4 aA = *(const float4*)&As[k][ty * 8];
            float4 aB = *(const float4*)&As[k][ty * 8 + 4];
            ull a2[8];
            a2[0] = dup2(aA.x); a2[1] = dup2(aA.y); a2[2] = dup2(aA.z); a2[3] = dup2(aA.w);
            a2[4] = dup2(aB.x); a2[5] = dup2(aB.y); a2[6] = dup2(aB.z); a2[7] = dup2(aB.w);
            ulonglong2 b01 = *(const ulonglong2*)&Bs[k][tx * 8];
            ulonglong2 b23 = *(const ulonglong2*)&Bs[k][tx * 8 + 4];
            ull b2[4] = { b01.x, b01.y, b23.x, b23.y };
#pragma unroll
            for (int i = 0; i < 8; i++) {
#pragma unroll
                for (int j = 0; j < 4; j++) fma2(c2[i][j], a2[i], b2[j]);
            }
        }
        if (kc < K) {
            __syncthreads();
            As[ac0 + 0][ar0] = av0.x; As[ac0 + 1][ar0] = av0.y;
            As[ac0 + 2][ar0] = av0.z; As[ac0 + 3][ar0] = av0.w;
            Bs[ac0 + 0][ar0] = bv0.x; Bs[ac0 + 1][ar0] = bv0.y;
            Bs[ac0 + 2][ar0] = bv0.z; Bs[ac0 + 3][ar0] = bv0.w;
            Bs[bc1 + 0][br1] = bv1.x; Bs[bc1 + 1][br1] = bv1.y;
            Bs[bc1 + 2][br1] = bv1.z; Bs[bc1 + 3][br1] = bv1.w;
            __syncthreads();
        }
    }

#pragma unroll
    for (int i = 0; i < 8; i++) {
        size_t r = (size_t)(row0 + ty * 8 + i);
        float* crow = C + r * (size_t)Ncols + col0 + tx * 8;
        float2 f0 = unpack2(c2[i][0]);
        float2 f1 = unpack2(c2[i][1]);
        float2 f2v = unpack2(c2[i][2]);
        float2 f3 = unpack2(c2[i][3]);
        float4 o0, o1;
        if (bias) {
            const float* bp = bias + col0 + tx * 8;
            o0 = make_float4(f0.x * scale + bp[0], f0.y * scale + bp[1],
                             f1.x * scale + bp[2], f1.y * scale + bp[3]);
            o1 = make_float4(f2v.x * scale + bp[4], f2v.y * scale + bp[5],
                             f3.x * scale + bp[6], f3.y * scale + bp[7]);
        } else {
            o0 = make_float4(f0.x * scale, f0.y * scale, f1.x * scale, f1.y * scale);
            o1 = make_float4(f2v.x * scale, f2v.y * scale, f3.x * scale, f3.y * scale);
        }
        *(float4*)&crow[0] = o0;
        *(float4*)&crow[4] = o1;
    }
}

// ---------------------------------------------------------------------------
// Pos-gate stream + fused epilogue (unchanged from R5 — HBM/amortization OK).
// ---------------------------------------------------------------------------
__global__ void __launch_bounds__(256, 2)
pos_epilogue_kernel(const float* __restrict__ PE, const float* __restrict__ Wg_w,
                    const float* __restrict__ Wg_b, float* __restrict__ out)
{
    __shared__ ull sh_wg2[EMB][HEADS];   // dup'd f32x2 per (e, h), 8 KB
    __shared__ float sh_b[HEADS];

    const int tid = threadIdx.x;
    for (int idx = tid; idx < EMB * HEADS; idx += 256) {
        int e = idx >> 4, h = idx & 15;
        sh_wg2[e][h] = dup2(Wg_w[h * EMB + e]);
    }
    if (tid < HEADS) sh_b[tid] = Wg_b[tid];
    __syncthreads();

    const int n = blockIdx.y;
    const int m = blockIdx.x * 1024 + tid * 4;

    const char* pe = (const char*)(PE + (size_t)n * MDIM + m);
    const size_t PLANE = (size_t)NDIM * MDIM * 4;   // bytes

    ull acc[HEADS][2];
#pragma unroll
    for (int h = 0; h < HEADS; h++) { acc[h][0] = 0ull; acc[h][1] = 0ull; }

    ull bx[4], by[4];
#pragma unroll
    for (int i = 0; i < 4; i++) ldcs_v2u64(pe + (size_t)i * PLANE, bx[i], by[i]);

    for (int eo = 0; eo < EMB; eo += 4) {
#pragma unroll
        for (int i = 0; i < 4; i++) {
            ull pvx = bx[i], pvy = by[i];
            int en_ = eo + 4 + i;
            if (en_ < EMB) ldcs_v2u64(pe + (size_t)en_ * PLANE, bx[i], by[i]);
            const ulonglong2* wrow = (const ulonglong2*)sh_wg2[eo + i];
#pragma unroll
            for (int h2 = 0; h2 < 8; h2++) {
                ulonglong2 w = wrow[h2];          // LDS.128: 2 heads
                fma2(acc[2 * h2][0],     w.x, pvx);
                fma2(acc[2 * h2][1],     w.x, pvy);
                fma2(acc[2 * h2 + 1][0], w.y, pvx);
                fma2(acc[2 * h2 + 1][1], w.y, pvy);
            }
        }
    }

    const float4 av = *(const float4*)&g_aff[(size_t)n * MDIM + m];
    const float L2E = 1.4426950408889634f;
    float en0 = exp2f(-av.x * L2E);
    float en1 = exp2f(-av.y * L2E);
    float en2 = exp2f(-av.z * L2E);
    float en3 = exp2f(-av.w * L2E);

    float s0 = 0.f, s1 = 0.f, s2 = 0.f, s3 = 0.f;
#pragma unroll
    for (int h = 0; h < HEADS; h++) {
        float bh = sh_b[h];
        float2 p0 = unpack2(acc[h][0]);
        float2 p1 = unpack2(acc[h][1]);
        float w;
        w = fmaxf(p0.x + bh, 0.f) + 1e-6f; s0 += __fdividef(w, w + en0);
        w = fmaxf(p0.y + bh, 0.f) + 1e-6f; s1 += __fdividef(w, w + en1);
        w = fmaxf(p1.x + bh, 0.f) + 1e-6f; s2 += __fdividef(w, w + en2);
        w = fmaxf(p1.y + bh, 0.f) + 1e-6f; s3 += __fdividef(w, w + en3);
    }

    float4 o;
    o.x = (s0 > 8.0f) ? 1.0f : 0.0f;
    o.y = (s1 > 8.0f) ? 1.0f : 0.0f;
    o.z = (s2 > 8.0f) ? 1.0f : 0.0f;
    o.w = (s3 > 8.0f) ? 1.0f : 0.0f;
    *(float4*)&out[(size_t)n * MDIM + m] = o;
}

// ---------------------------------------------------------------------------
extern "C" void kernel_launch(void* const* d_in, const int* in_sizes, int n_in,
                              void* d_out, int out_size)
{
    (void)in_sizes; (void)n_in; (void)out_size;
    const float* ref_feat = (const float*)d_in[0];
    const float* sup_feat = (const float*)d_in[1];
    const float* PE       = (const float*)d_in[2];
    const float* Wg_w     = (const float*)d_in[3];
    const float* Wg_b     = (const float*)d_in[4];
    const float* Wq_w     = (const float*)d_in[5];
    const float* Wq_b     = (const float*)d_in[6];
    const float* Wk_w     = (const float*)d_in[7];
    const float* Wk_b     = (const float*)d_in[8];
    float* out = (float*)d_out;

    // fused q/k GEMM: z=0 -> q = ref@WqT+bq, z=1 -> k = sup@WkT+bk
    gemm_nt_kernel<<<dim3(DDIM / BN, NDIM / BM, 2), 512>>>(
        ref_feat, Wq_w, Wq_b, sup_feat, Wk_w, Wk_b, DDIM, 1.0f, 0);
    // aff = (q @ kT) / 32
    gemm_nt_kernel<<<dim3(MDIM / BN, NDIM / BM, 1), 512>>>(
        nullptr, nullptr, nullptr, nullptr, nullptr, nullptr, MDIM, 0.03125f, 2);
    // pos stream + fused epilogue
    pos_epilogue_kernel<<<dim3(MDIM / 1024, NDIM), 256>>>(PE, Wg_w, Wg_b, out);
}